// round 1
// baseline (speedup 1.0000x reference)
#include <cuda_runtime.h>
#include <math.h>

#define NH     16
#define NKV    4
#define HDIM   128
#define BATCH  2
#define SEQ    2048
#define DMODEL 2048
#define NTOK   (BATCH*SEQ)

#define QB 16
#define CK 128
#define SMEM_ATTN ((QB*SEQ + QB*HDIM + CK*HDIM) * (int)sizeof(float))

// scratch (no cudaMalloc allowed)
static __device__ float g_q[NTOK * NH * HDIM];     // [tok, H, HD]
static __device__ float g_k[NTOK * NKV * HDIM];    // [tok, HKV, HD]
static __device__ float g_v[NTOK * NKV * HDIM];
static __device__ float g_ctx[NTOK * NH * HDIM];   // [tok, H, HD]

// ---------------------------------------------------------------------------
// SGEMM: C[M,N] = A[M,K] @ B[K,N], all row-major. 128x128 block, BK=8,
// 256 threads, 8x8 per thread (split 4+4 for conflict-free smem reads).
// ---------------------------------------------------------------------------
__global__ void __launch_bounds__(256) sgemm_kernel(
    const float* __restrict__ A, const float* __restrict__ Bm,
    float* __restrict__ C, int M, int N, int K) {
  __shared__ float As[8][128];
  __shared__ float Bs[8][128];
  int tid = threadIdx.x;
  int bm = blockIdx.y * 128;
  int bn = blockIdx.x * 128;
  int tx = tid & 15, ty = tid >> 4;

  float acc[8][8];
  #pragma unroll
  for (int i = 0; i < 8; i++)
    #pragma unroll
    for (int j = 0; j < 8; j++) acc[i][j] = 0.f;

  int aRow = tid >> 1, aCol = (tid & 1) * 4;    // A tile 128x8
  int bRow = tid >> 5, bCol = (tid & 31) * 4;   // B tile 8x128
  const float* Aptr = A + (size_t)(bm + aRow) * K + aCol;
  const float* Bptr = Bm + (size_t)bRow * N + bn + bCol;

  for (int k0 = 0; k0 < K; k0 += 8) {
    float4 a4 = *(const float4*)(Aptr + k0);
    float4 b4 = *(const float4*)(Bptr + (size_t)k0 * N);
    As[aCol + 0][aRow] = a4.x;
    As[aCol + 1][aRow] = a4.y;
    As[aCol + 2][aRow] = a4.z;
    As[aCol + 3][aRow] = a4.w;
    *(float4*)&Bs[bRow][bCol] = b4;
    __syncthreads();
    #pragma unroll
    for (int kk = 0; kk < 8; kk++) {
      float4 m0 = *(const float4*)&As[kk][ty * 4];
      float4 m1 = *(const float4*)&As[kk][64 + ty * 4];
      float4 n0 = *(const float4*)&Bs[kk][tx * 4];
      float4 n1 = *(const float4*)&Bs[kk][64 + tx * 4];
      float rm[8] = {m0.x, m0.y, m0.z, m0.w, m1.x, m1.y, m1.z, m1.w};
      float rn[8] = {n0.x, n0.y, n0.z, n0.w, n1.x, n1.y, n1.z, n1.w};
      #pragma unroll
      for (int i = 0; i < 8; i++)
        #pragma unroll
        for (int j = 0; j < 8; j++)
          acc[i][j] += rm[i] * rn[j];
    }
    __syncthreads();
  }

  #pragma unroll
  for (int i = 0; i < 8; i++) {
    int row = bm + ((i < 4) ? (ty * 4 + i) : (64 + ty * 4 + (i - 4)));
    float4 c0 = {acc[i][0], acc[i][1], acc[i][2], acc[i][3]};
    float4 c1 = {acc[i][4], acc[i][5], acc[i][6], acc[i][7]};
    *(float4*)(C + (size_t)row * N + bn + tx * 4) = c0;
    *(float4*)(C + (size_t)row * N + bn + 64 + tx * 4) = c1;
  }
}

// ---------------------------------------------------------------------------
// RoPE (interleaved pairs) + L2 norm. One 64-thread block per (token, row).
// rows 0..15 -> q heads, 16..19 -> k heads.
// ---------------------------------------------------------------------------
__global__ void __launch_bounds__(64) rope_norm_kernel() {
  int tok = blockIdx.x;
  int r = blockIdx.y;
  float* base = (r < NH)
      ? g_q + ((size_t)tok * NH + r) * HDIM
      : g_k + ((size_t)tok * NKV + (r - NH)) * HDIM;
  int pos = tok & (SEQ - 1);
  int i = threadIdx.x;  // pair index 0..63
  float t0 = base[2 * i], t1 = base[2 * i + 1];
  float inv = powf(10000.0f, -(float)(2 * i) * (1.0f / 128.0f));
  float ang = (float)pos * inv;
  float sn, cs;
  sincosf(ang, &sn, &cs);
  float r0 = t0 * cs - t1 * sn;
  float r1 = t0 * sn + t1 * cs;
  float ss = r0 * r0 + r1 * r1;
  #pragma unroll
  for (int o = 16; o; o >>= 1) ss += __shfl_xor_sync(0xffffffffu, ss, o);
  __shared__ float part[2];
  if ((i & 31) == 0) part[i >> 5] = ss;
  __syncthreads();
  float sc = rsqrtf((part[0] + part[1]) * (1.0f / 128.0f) + 1e-6f);
  base[2 * i] = r0 * sc;
  base[2 * i + 1] = r1 * sc;
}

// ---------------------------------------------------------------------------
// Attention: one block per (b, h, 16-query tile). Scores tile in smem,
// exact two-pass softmax, writes attn probs (0 above diagonal), AV accum.
// K/V chunks XOR-swizzled at float4 granularity for conflict-free LDS.128.
// ---------------------------------------------------------------------------
__global__ void __launch_bounds__(256) attn_kernel(float* __restrict__ attn_out,
                                                   int write_attn) {
  extern __shared__ float sm[];
  float* s_scores = sm;                                   // QB*SEQ
  float4* s_q4 = (float4*)(sm + QB * SEQ);                // QB*32
  float4* s_kv4 = (float4*)(sm + QB * SEQ + QB * HDIM);   // CK*32
  __shared__ float s_m[QB], s_inv[QB];

  int qb = gridDim.x - 1 - blockIdx.x;  // heavy (long-row) tiles first
  int h = blockIdx.y, b = blockIdx.z;
  int hk = h >> 2;  // GQA: n_rep = 4
  int tid = threadIdx.x;
  int lane5 = tid & 31;
  int q0 = (tid >> 5) * 2;  // warp -> query pair
  int kend = qb * QB + QB;
  const float SC = 0.08838834764831845f;  // 1/sqrt(128)

  // load q tile
  {
    const float* qbase = g_q + ((size_t)((size_t)b * SEQ + qb * QB) * NH + h) * HDIM;
    for (int idx = tid; idx < QB * 32; idx += 256) {
      int qi = idx >> 5, g = idx & 31;
      s_q4[idx] = *(const float4*)(qbase + (size_t)qi * NH * HDIM + g * 4);
    }
  }

  // ---- score phase ----
  for (int kc = 0; kc < kend; kc += CK) {
    __syncthreads();
    const float* kb = g_k + ((size_t)((size_t)b * SEQ + kc) * NKV + hk) * HDIM;
    for (int idx = tid; idx < CK * 32; idx += 256) {
      int j = idx >> 5, g = idx & 31;
      s_kv4[(j << 5) | (g ^ (j & 31))] =
          *(const float4*)(kb + (size_t)j * NKV * HDIM + g * 4);
    }
    __syncthreads();
    float acc[2][4];
    #pragma unroll
    for (int kk = 0; kk < 4; kk++) { acc[0][kk] = 0.f; acc[1][kk] = 0.f; }
    #pragma unroll 8
    for (int dg = 0; dg < 32; dg++) {
      float4 qa = s_q4[(q0 << 5) + dg];
      float4 qc = s_q4[((q0 + 1) << 5) + dg];
      #pragma unroll
      for (int kk = 0; kk < 4; kk++) {
        int j = lane5 + (kk << 5);
        float4 kv = s_kv4[(j << 5) | (dg ^ lane5)];
        acc[0][kk] += qa.x * kv.x + qa.y * kv.y + qa.z * kv.z + qa.w * kv.w;
        acc[1][kk] += qc.x * kv.x + qc.y * kv.y + qc.z * kv.z + qc.w * kv.w;
      }
    }
    #pragma unroll
    for (int kk = 0; kk < 4; kk++) {
      int jg = kc + lane5 + (kk << 5);
      #pragma unroll
      for (int qq = 0; qq < 2; qq++) {
        int qs = qb * QB + q0 + qq;
        s_scores[(q0 + qq) * SEQ + jg] = (jg <= qs) ? acc[qq][kk] * SC : -1e30f;
      }
    }
  }
  __syncthreads();

  // ---- softmax reduce (16 threads per query row) ----
  {
    int qi = tid >> 4, r = tid & 15;
    float m = -1e30f;
    for (int j = r; j < kend; j += 16) m = fmaxf(m, s_scores[qi * SEQ + j]);
    #pragma unroll
    for (int o = 8; o; o >>= 1) m = fmaxf(m, __shfl_xor_sync(0xffffffffu, m, o));
    float s = 0.f;
    for (int j = r; j < kend; j += 16) s += __expf(s_scores[qi * SEQ + j] - m);
    #pragma unroll
    for (int o = 8; o; o >>= 1) s += __shfl_xor_sync(0xffffffffu, s, o);
    if (r == 0) { s_m[qi] = m; s_inv[qi] = 1.0f / s; }
  }
  __syncthreads();

  // ---- normalize + write attn (full rows incl. causal zeros) ----
  {
    float* ab = attn_out + ((size_t)(b * NH + h) * SEQ + (size_t)qb * QB) * SEQ;
    for (int idx = tid; idx < QB * SEQ; idx += 256) {
      int qi = idx >> 11;
      int j = idx & (SEQ - 1);
      float p = 0.f;
      if (j < kend) {
        p = __expf(s_scores[idx] - s_m[qi]) * s_inv[qi];
        s_scores[idx] = p;
      }
      if (write_attn) ab[(size_t)qi * SEQ + j] = p;
    }
  }
  __syncthreads();

  // ---- AV phase ----
  int dg = lane5;
  float4 o0 = {0, 0, 0, 0}, o1 = {0, 0, 0, 0};
  for (int kc = 0; kc < kend; kc += CK) {
    __syncthreads();
    const float* vb = g_v + ((size_t)((size_t)b * SEQ + kc) * NKV + hk) * HDIM;
    for (int idx = tid; idx < CK * 32; idx += 256) {
      int j = idx >> 5, g = idx & 31;
      s_kv4[(j << 5) | (g ^ (j & 31))] =
          *(const float4*)(vb + (size_t)j * NKV * HDIM + g * 4);
    }
    __syncthreads();
    int jmax = min(CK, kend - kc);
    #pragma unroll 4
    for (int j = 0; j < jmax; j++) {
      float p0 = s_scores[q0 * SEQ + kc + j];
      float p1 = s_scores[(q0 + 1) * SEQ + kc + j];
      float4 vv = s_kv4[(j << 5) | (dg ^ (j & 31))];
      o0.x += p0 * vv.x; o0.y += p0 * vv.y; o0.z += p0 * vv.z; o0.w += p0 * vv.w;
      o1.x += p1 * vv.x; o1.y += p1 * vv.y; o1.z += p1 * vv.z; o1.w += p1 * vv.w;
    }
  }
  // write ctx [tok, H, HD]
  {
    int qs0 = qb * QB + q0;
    float* cb = g_ctx + ((size_t)((size_t)b * SEQ + qs0) * NH + h) * HDIM + dg * 4;
    *(float4*)cb = o0;
    *(float4*)(cb + NH * HDIM) = o1;
  }
}

// ---------------------------------------------------------------------------
extern "C" void kernel_launch(void* const* d_in, const int* in_sizes, int n_in,
                              void* d_out, int out_size) {
  const float* x  = (const float*)d_in[0];
  const float* Wq = (const float*)d_in[1];
  const float* Wk = (const float*)d_in[2];
  const float* Wv = (const float*)d_in[3];
  const float* Wo = (const float*)d_in[4];
  float* out = (float*)d_out;
  float* attn = out + (size_t)NTOK * DMODEL;
  long long need = (long long)NTOK * DMODEL + (long long)BATCH * NH * SEQ * SEQ;
  int write_attn = ((long long)out_size >= need) ? 1 : 0;

  float *gq, *gk, *gv, *gctx;
  cudaGetSymbolAddress((void**)&gq, g_q);
  cudaGetSymbolAddress((void**)&gk, g_k);
  cudaGetSymbolAddress((void**)&gv, g_v);
  cudaGetSymbolAddress((void**)&gctx, g_ctx);

  cudaFuncSetAttribute(attn_kernel, cudaFuncAttributeMaxDynamicSharedMemorySize,
                       SMEM_ATTN);

  // QKV projections
  sgemm_kernel<<<dim3(DMODEL / 128, NTOK / 128), 256>>>(x, Wq, gq, NTOK, NH * HDIM, DMODEL);
  sgemm_kernel<<<dim3((NKV * HDIM) / 128, NTOK / 128), 256>>>(x, Wk, gk, NTOK, NKV * HDIM, DMODEL);
  sgemm_kernel<<<dim3((NKV * HDIM) / 128, NTOK / 128), 256>>>(x, Wv, gv, NTOK, NKV * HDIM, DMODEL);

  // RoPE + l2norm on q and k
  rope_norm_kernel<<<dim3(NTOK, NH + NKV), 64>>>();

  // attention (+ attn probability output, ctx accumulation)
  attn_kernel<<<dim3(SEQ / QB, NH, BATCH), 256, SMEM_ATTN>>>(attn, write_attn);

  // output projection
  sgemm_kernel<<<dim3(DMODEL / 128, NTOK / 128), 256>>>(gctx, Wo, out, NTOK, DMODEL, DMODEL);
}

// round 3
// speedup vs baseline: 1.4303x; 1.4303x over previous
#include <cuda_runtime.h>
#include <cuda_bf16.h>
#include <math.h>
#include <stdint.h>

#define NH     16
#define NKV    4
#define HDIM   128
#define BATCH  2
#define SEQ    2048
#define DMODEL 2048
#define NTOK   (BATCH*SEQ)

#define QB 16
#define CK 128
#define SMEM_ATTN ((QB*SEQ + QB*HDIM + CK*HDIM) * (int)sizeof(float))

// ---------------------------------------------------------------------------
// scratch (no cudaMalloc allowed)
// ---------------------------------------------------------------------------
static __device__ float g_q[NTOK * NH * HDIM];     // [tok, H, HD]
static __device__ float g_k[NTOK * NKV * HDIM];    // [tok, HKV, HD]
static __device__ float g_v[NTOK * NKV * HDIM];
static __device__ float g_ctx[NTOK * NH * HDIM];   // [tok, H, HD]

static __device__ __nv_bfloat16 g_xh[NTOK * DMODEL];
static __device__ __nv_bfloat16 g_xl[NTOK * DMODEL];
static __device__ __nv_bfloat16 g_cth[NTOK * DMODEL];
static __device__ __nv_bfloat16 g_ctl[NTOK * DMODEL];
// transposed weights [N, K]
static __device__ __nv_bfloat16 g_wqh[DMODEL * (NH*HDIM)];
static __device__ __nv_bfloat16 g_wql[DMODEL * (NH*HDIM)];
static __device__ __nv_bfloat16 g_wkh[DMODEL * (NKV*HDIM)];
static __device__ __nv_bfloat16 g_wkl[DMODEL * (NKV*HDIM)];
static __device__ __nv_bfloat16 g_wvh[DMODEL * (NKV*HDIM)];
static __device__ __nv_bfloat16 g_wvl[DMODEL * (NKV*HDIM)];
static __device__ __nv_bfloat16 g_woh[DMODEL * DMODEL];
static __device__ __nv_bfloat16 g_wol[DMODEL * DMODEL];

// ---------------------------------------------------------------------------
// helpers: generic-PTX tensor path (ldmatrix + mma.sync + cp.async)
// ---------------------------------------------------------------------------
__device__ __forceinline__ uint32_t smem_u32(const void* p) {
  uint32_t a;
  asm("{ .reg .u64 t; cvta.to.shared.u64 t, %1; cvt.u32.u64 %0, t; }" : "=r"(a) : "l"(p));
  return a;
}

#define LDSM4(R, addr)                                                        \
  asm volatile("ldmatrix.sync.aligned.m8n8.x4.shared.b16 {%0,%1,%2,%3}, [%4];"\
    : "=r"((R)[0]), "=r"((R)[1]), "=r"((R)[2]), "=r"((R)[3]) : "r"(addr))

#define MMA16816(D, A, b0v, b1v)                                              \
  asm volatile("mma.sync.aligned.m16n8k16.row.col.f32.bf16.bf16.f32 "         \
    "{%0,%1,%2,%3}, {%4,%5,%6,%7}, {%8,%9}, {%0,%1,%2,%3};"                   \
    : "+f"((D)[0]), "+f"((D)[1]), "+f"((D)[2]), "+f"((D)[3])                  \
    : "r"((A)[0]), "r"((A)[1]), "r"((A)[2]), "r"((A)[3]), "r"(b0v), "r"(b1v))

#define CP_ASYNC16(dst, src) \
  asm volatile("cp.async.cg.shared.global [%0], [%1], 16;" :: "r"(dst), "l"(src))
#define CP_COMMIT() asm volatile("cp.async.commit_group;")

// ---------------------------------------------------------------------------
// split fp32 -> bf16 hi/lo (elementwise)
// ---------------------------------------------------------------------------
__global__ void __launch_bounds__(256) split_kernel(const float* __restrict__ src,
    __nv_bfloat16* __restrict__ hi, __nv_bfloat16* __restrict__ lo, int n) {
  int i = blockIdx.x * 256 + threadIdx.x;
  if (i < n) {
    float v = src[i];
    __nv_bfloat16 h = __float2bfloat16(v);
    hi[i] = h;
    lo[i] = __float2bfloat16(v - __bfloat162float(h));
  }
}

// W [K,N] fp32 -> transposed bf16 hi/lo [N,K]
__global__ void __launch_bounds__(256) wsplit_kernel(const float* __restrict__ W,
    __nv_bfloat16* __restrict__ th, __nv_bfloat16* __restrict__ tl, int K, int N) {
  __shared__ float t[32][33];
  int n0 = blockIdx.x * 32, k0 = blockIdx.y * 32;
  int x = threadIdx.x, y = threadIdx.y;  // 32 x 8
  #pragma unroll
  for (int i = 0; i < 4; i++)
    t[y * 4 + i][x] = W[(size_t)(k0 + y * 4 + i) * N + n0 + x];
  __syncthreads();
  #pragma unroll
  for (int i = 0; i < 4; i++) {
    int n = n0 + y * 4 + i;
    float v = t[x][y * 4 + i];
    __nv_bfloat16 h = __float2bfloat16(v);
    th[(size_t)n * K + k0 + x] = h;
    tl[(size_t)n * K + k0 + x] = __float2bfloat16(v - __bfloat162float(h));
  }
}

// ---------------------------------------------------------------------------
// mma.sync GEMM with bf16x3 split: C[M,N] = A[M,K] @ B^T (B stored [N,K]).
// 128x128 CTA tile, BK=32, 8 warps (4M x 2N), warp tile 32x64.
// Smem rows padded to 80B -> conflict-free ldmatrix. Double-buffered cp.async.
// ---------------------------------------------------------------------------
#define GBM 128
#define GBN 128
#define GBK 32
#define RSTRIDE 80                     // bytes per smem row (64 data + 16 pad)
#define TILE_BYTES (128 * RSTRIDE)     // 10240
#define CH_BYTES (4 * TILE_BYTES)      // Ah, Al, Bh, Bl
#define GEMM_SMEM (2 * CH_BYTES)       // 81920

__global__ void __launch_bounds__(256) gemm3_kernel(
    const __nv_bfloat16* __restrict__ Ah, const __nv_bfloat16* __restrict__ Al,
    const __nv_bfloat16* __restrict__ Bh, const __nv_bfloat16* __restrict__ Bl,
    float* __restrict__ C, int K, int N) {
  extern __shared__ char smem[];
  uint32_t sbase = smem_u32(smem);
  int tid = threadIdx.x;
  int wid = tid >> 5, lane = tid & 31;
  int wm = wid >> 1, wn = wid & 1;     // 4 x 2 warp grid
  int bm = blockIdx.y * GBM, bn = blockIdx.x * GBN;
  int nc = K / GBK;

  const __nv_bfloat16* srcs[4] = {Ah, Al, Bh, Bl};
  int rbase[4] = {bm, bm, bn, bn};

  auto load_chunk = [&](int c, int buf) {
    int k0 = c * GBK;
    #pragma unroll
    for (int i = 0; i < 8; i++) {
      int idx = tid + i * 256;          // 0..2047
      int t = idx >> 9;                 // tile 0..3
      int r = (idx >> 2) & 127;         // row
      int g = idx & 3;                  // 16B group
      uint32_t dst = sbase + buf * CH_BYTES + t * TILE_BYTES + r * RSTRIDE + g * 16;
      const __nv_bfloat16* src = srcs[t] + (size_t)(rbase[t] + r) * K + k0 + g * 8;
      CP_ASYNC16(dst, src);
    }
    CP_COMMIT();
  };

  float acc[2][8][4];
  #pragma unroll
  for (int mi = 0; mi < 2; mi++)
    #pragma unroll
    for (int ni = 0; ni < 8; ni++)
      #pragma unroll
      for (int j = 0; j < 4; j++) acc[mi][ni][j] = 0.f;

  load_chunk(0, 0);

  int lrow = lane & 15, lk8 = (lane >> 4) * 8;

  for (int c = 0; c < nc; c++) {
    if (c + 1 < nc) {
      load_chunk(c + 1, (c + 1) & 1);
      asm volatile("cp.async.wait_group 1;");
    } else {
      asm volatile("cp.async.wait_group 0;");
    }
    __syncthreads();

    uint32_t b0 = sbase + (c & 1) * CH_BYTES;
    uint32_t aH = b0, aL = b0 + TILE_BYTES;
    uint32_t bH = b0 + 2 * TILE_BYTES, bL = b0 + 3 * TILE_BYTES;

    #pragma unroll
    for (int kk = 0; kk < GBK; kk += 16) {
      uint32_t ah[2][4], al[2][4];
      uint32_t aoff = (uint32_t)(wm * 32 + lrow) * RSTRIDE + (kk + lk8) * 2;
      LDSM4(ah[0], aH + aoff);
      LDSM4(ah[1], aH + aoff + 16 * RSTRIDE);
      LDSM4(al[0], aL + aoff);
      LDSM4(al[1], aL + aoff + 16 * RSTRIDE);
      #pragma unroll
      for (int p = 0; p < 4; p++) {
        uint32_t boff = (uint32_t)(wn * 64 + p * 16 + lrow) * RSTRIDE + (kk + lk8) * 2;
        uint32_t h[4], l[4];
        LDSM4(h, bH + boff);
        LDSM4(l, bL + boff);
        // ntile 2p -> {r0, r2}; ntile 2p+1 -> {r1, r3}
        #pragma unroll
        for (int mi = 0; mi < 2; mi++) {
          MMA16816(acc[mi][2 * p],     ah[mi], h[0], h[2]);
          MMA16816(acc[mi][2 * p],     ah[mi], l[0], l[2]);
          MMA16816(acc[mi][2 * p],     al[mi], h[0], h[2]);
          MMA16816(acc[mi][2 * p + 1], ah[mi], h[1], h[3]);
          MMA16816(acc[mi][2 * p + 1], ah[mi], l[1], l[3]);
          MMA16816(acc[mi][2 * p + 1], al[mi], h[1], h[3]);
        }
      }
    }
    __syncthreads();
  }

  // epilogue
  int gid = lane >> 2, cid = lane & 3;
  #pragma unroll
  for (int mi = 0; mi < 2; mi++)
    #pragma unroll
    for (int ni = 0; ni < 8; ni++) {
      int row = bm + wm * 32 + mi * 16 + gid;
      int col = bn + wn * 64 + ni * 8 + cid * 2;
      float2 v0 = {acc[mi][ni][0], acc[mi][ni][1]};
      float2 v1 = {acc[mi][ni][2], acc[mi][ni][3]};
      *(float2*)(C + (size_t)row * N + col) = v0;
      *(float2*)(C + (size_t)(row + 8) * N + col) = v1;
    }
}

// ---------------------------------------------------------------------------
// RoPE (interleaved pairs) + L2 norm
// ---------------------------------------------------------------------------
__global__ void __launch_bounds__(64) rope_norm_kernel() {
  int tok = blockIdx.x;
  int r = blockIdx.y;
  float* base = (r < NH)
      ? g_q + ((size_t)tok * NH + r) * HDIM
      : g_k + ((size_t)tok * NKV + (r - NH)) * HDIM;
  int pos = tok & (SEQ - 1);
  int i = threadIdx.x;  // pair index 0..63
  float t0 = base[2 * i], t1 = base[2 * i + 1];
  // 10000^(-2i/128) = exp2(-2i/128 * log2(10000))
  float inv = exp2f((float)(2 * i) * (-13.287712379549449f / 128.0f));
  float ang = (float)pos * inv;
  float sn, cs;
  sincosf(ang, &sn, &cs);
  float r0 = t0 * cs - t1 * sn;
  float r1 = t0 * sn + t1 * cs;
  float ss = r0 * r0 + r1 * r1;
  #pragma unroll
  for (int o = 16; o; o >>= 1) ss += __shfl_xor_sync(0xffffffffu, ss, o);
  __shared__ float part[2];
  if ((i & 31) == 0) part[i >> 5] = ss;
  __syncthreads();
  float sc = rsqrtf((part[0] + part[1]) * (1.0f / 128.0f) + 1e-6f);
  base[2 * i] = r0 * sc;
  base[2 * i + 1] = r1 * sc;
}

// ---------------------------------------------------------------------------
// Attention (SIMT, fp32) — unchanged
// ---------------------------------------------------------------------------
__global__ void __launch_bounds__(256) attn_kernel(float* __restrict__ attn_out,
                                                   int write_attn) {
  extern __shared__ float sm[];
  float* s_scores = sm;                                   // QB*SEQ
  float4* s_q4 = (float4*)(sm + QB * SEQ);                // QB*32
  float4* s_kv4 = (float4*)(sm + QB * SEQ + QB * HDIM);   // CK*32
  __shared__ float s_m[QB], s_inv[QB];

  int qb = gridDim.x - 1 - blockIdx.x;
  int h = blockIdx.y, b = blockIdx.z;
  int hk = h >> 2;
  int tid = threadIdx.x;
  int lane5 = tid & 31;
  int q0 = (tid >> 5) * 2;
  int kend = qb * QB + QB;
  const float SC = 0.08838834764831845f;

  {
    const float* qbase = g_q + ((size_t)((size_t)b * SEQ + qb * QB) * NH + h) * HDIM;
    for (int idx = tid; idx < QB * 32; idx += 256) {
      int qi = idx >> 5, g = idx & 31;
      s_q4[idx] = *(const float4*)(qbase + (size_t)qi * NH * HDIM + g * 4);
    }
  }

  for (int kc = 0; kc < kend; kc += CK) {
    __syncthreads();
    const float* kb = g_k + ((size_t)((size_t)b * SEQ + kc) * NKV + hk) * HDIM;
    for (int idx = tid; idx < CK * 32; idx += 256) {
      int j = idx >> 5, g = idx & 31;
      s_kv4[(j << 5) | (g ^ (j & 31))] =
          *(const float4*)(kb + (size_t)j * NKV * HDIM + g * 4);
    }
    __syncthreads();
    float acc[2][4];
    #pragma unroll
    for (int kk = 0; kk < 4; kk++) { acc[0][kk] = 0.f; acc[1][kk] = 0.f; }
    #pragma unroll 8
    for (int dg = 0; dg < 32; dg++) {
      float4 qa = s_q4[(q0 << 5) + dg];
      float4 qc = s_q4[((q0 + 1) << 5) + dg];
      #pragma unroll
      for (int kk = 0; kk < 4; kk++) {
        int j = lane5 + (kk << 5);
        float4 kv = s_kv4[(j << 5) | (dg ^ lane5)];
        acc[0][kk] += qa.x * kv.x + qa.y * kv.y + qa.z * kv.z + qa.w * kv.w;
        acc[1][kk] += qc.x * kv.x + qc.y * kv.y + qc.z * kv.z + qc.w * kv.w;
      }
    }
    #pragma unroll
    for (int kk = 0; kk < 4; kk++) {
      int jg = kc + lane5 + (kk << 5);
      #pragma unroll
      for (int qq = 0; qq < 2; qq++) {
        int qs = qb * QB + q0 + qq;
        s_scores[(q0 + qq) * SEQ + jg] = (jg <= qs) ? acc[qq][kk] * SC : -1e30f;
      }
    }
  }
  __syncthreads();

  {
    int qi = tid >> 4, r = tid & 15;
    float m = -1e30f;
    for (int j = r; j < kend; j += 16) m = fmaxf(m, s_scores[qi * SEQ + j]);
    #pragma unroll
    for (int o = 8; o; o >>= 1) m = fmaxf(m, __shfl_xor_sync(0xffffffffu, m, o));
    float s = 0.f;
    for (int j = r; j < kend; j += 16) s += __expf(s_scores[qi * SEQ + j] - m);
    #pragma unroll
    for (int o = 8; o; o >>= 1) s += __shfl_xor_sync(0xffffffffu, s, o);
    if (r == 0) { s_m[qi] = m; s_inv[qi] = 1.0f / s; }
  }
  __syncthreads();

  {
    float* ab = attn_out + ((size_t)(b * NH + h) * SEQ + (size_t)qb * QB) * SEQ;
    for (int idx = tid; idx < QB * SEQ; idx += 256) {
      int qi = idx >> 11;
      int j = idx & (SEQ - 1);
      float p = 0.f;
      if (j < kend) {
        p = __expf(s_scores[idx] - s_m[qi]) * s_inv[qi];
        s_scores[idx] = p;
      }
      if (write_attn) ab[(size_t)qi * SEQ + j] = p;
    }
  }
  __syncthreads();

  int dg = lane5;
  float4 o0 = {0, 0, 0, 0}, o1 = {0, 0, 0, 0};
  for (int kc = 0; kc < kend; kc += CK) {
    __syncthreads();
    const float* vb = g_v + ((size_t)((size_t)b * SEQ + kc) * NKV + hk) * HDIM;
    for (int idx = tid; idx < CK * 32; idx += 256) {
      int j = idx >> 5, g = idx & 31;
      s_kv4[(j << 5) | (g ^ (j & 31))] =
          *(const float4*)(vb + (size_t)j * NKV * HDIM + g * 4);
    }
    __syncthreads();
    int jmax = min(CK, kend - kc);
    #pragma unroll 4
    for (int j = 0; j < jmax; j++) {
      float p0 = s_scores[q0 * SEQ + kc + j];
      float p1 = s_scores[(q0 + 1) * SEQ + kc + j];
      float4 vv = s_kv4[(j << 5) | (dg ^ (j & 31))];
      o0.x += p0 * vv.x; o0.y += p0 * vv.y; o0.z += p0 * vv.z; o0.w += p0 * vv.w;
      o1.x += p1 * vv.x; o1.y += p1 * vv.y; o1.z += p1 * vv.z; o1.w += p1 * vv.w;
    }
  }
  {
    int qs0 = qb * QB + q0;
    float* cb = g_ctx + ((size_t)((size_t)b * SEQ + qs0) * NH + h) * HDIM + dg * 4;
    *(float4*)cb = o0;
    *(float4*)(cb + NH * HDIM) = o1;
  }
}

// ---------------------------------------------------------------------------
extern "C" void kernel_launch(void* const* d_in, const int* in_sizes, int n_in,
                              void* d_out, int out_size) {
  const float* x  = (const float*)d_in[0];
  const float* Wq = (const float*)d_in[1];
  const float* Wk = (const float*)d_in[2];
  const float* Wv = (const float*)d_in[3];
  const float* Wo = (const float*)d_in[4];
  float* out = (float*)d_out;
  float* attn = out + (size_t)NTOK * DMODEL;
  long long need = (long long)NTOK * DMODEL + (long long)BATCH * NH * SEQ * SEQ;
  int write_attn = ((long long)out_size >= need) ? 1 : 0;

  float *gq, *gk, *gv, *gctx;
  __nv_bfloat16 *xh, *xl, *cth, *ctl;
  __nv_bfloat16 *wqh, *wql, *wkh, *wkl, *wvh, *wvl, *woh, *wol;
  cudaGetSymbolAddress((void**)&gq, g_q);
  cudaGetSymbolAddress((void**)&gk, g_k);
  cudaGetSymbolAddress((void**)&gv, g_v);
  cudaGetSymbolAddress((void**)&gctx, g_ctx);
  cudaGetSymbolAddress((void**)&xh, g_xh);
  cudaGetSymbolAddress((void**)&xl, g_xl);
  cudaGetSymbolAddress((void**)&cth, g_cth);
  cudaGetSymbolAddress((void**)&ctl, g_ctl);
  cudaGetSymbolAddress((void**)&wqh, g_wqh);
  cudaGetSymbolAddress((void**)&wql, g_wql);
  cudaGetSymbolAddress((void**)&wkh, g_wkh);
  cudaGetSymbolAddress((void**)&wkl, g_wkl);
  cudaGetSymbolAddress((void**)&wvh, g_wvh);
  cudaGetSymbolAddress((void**)&wvl, g_wvl);
  cudaGetSymbolAddress((void**)&woh, g_woh);
  cudaGetSymbolAddress((void**)&wol, g_wol);

  cudaFuncSetAttribute(attn_kernel, cudaFuncAttributeMaxDynamicSharedMemorySize,
                       SMEM_ATTN);
  cudaFuncSetAttribute(gemm3_kernel, cudaFuncAttributeMaxDynamicSharedMemorySize,
                       GEMM_SMEM);

  // prep: split x, split+transpose weights
  {
    int n = NTOK * DMODEL;
    split_kernel<<<(n + 255) / 256, 256>>>(x, xh, xl, n);
  }
  wsplit_kernel<<<dim3((NH*HDIM)/32, DMODEL/32), dim3(32, 8)>>>(Wq, wqh, wql, DMODEL, NH*HDIM);
  wsplit_kernel<<<dim3((NKV*HDIM)/32, DMODEL/32), dim3(32, 8)>>>(Wk, wkh, wkl, DMODEL, NKV*HDIM);
  wsplit_kernel<<<dim3((NKV*HDIM)/32, DMODEL/32), dim3(32, 8)>>>(Wv, wvh, wvl, DMODEL, NKV*HDIM);
  wsplit_kernel<<<dim3(DMODEL/32, DMODEL/32), dim3(32, 8)>>>(Wo, woh, wol, DMODEL, DMODEL);

  // QKV projections (mma.sync bf16x3)
  gemm3_kernel<<<dim3((NH*HDIM)/GBN, NTOK/GBM), 256, GEMM_SMEM>>>(xh, xl, wqh, wql, gq, DMODEL, NH*HDIM);
  gemm3_kernel<<<dim3((NKV*HDIM)/GBN, NTOK/GBM), 256, GEMM_SMEM>>>(xh, xl, wkh, wkl, gk, DMODEL, NKV*HDIM);
  gemm3_kernel<<<dim3((NKV*HDIM)/GBN, NTOK/GBM), 256, GEMM_SMEM>>>(xh, xl, wvh, wvl, gv, DMODEL, NKV*HDIM);

  // RoPE + l2norm on q and k
  rope_norm_kernel<<<dim3(NTOK, NH + NKV), 64>>>();

  // attention (+ attn probability output, ctx accumulation)
  attn_kernel<<<dim3(SEQ / QB, NH, BATCH), 256, SMEM_ATTN>>>(attn, write_attn);

  // output projection
  {
    int n = NTOK * DMODEL;
    split_kernel<<<(n + 255) / 256, 256>>>(gctx, cth, ctl, n);
  }
  gemm3_kernel<<<dim3(DMODEL/GBN, NTOK/GBM), 256, GEMM_SMEM>>>(cth, ctl, woh, wol, out, DMODEL, DMODEL);
}

// round 4
// speedup vs baseline: 2.1230x; 1.4843x over previous
#include <cuda_runtime.h>
#include <cuda_bf16.h>
#include <math.h>
#include <stdint.h>

#define NH     16
#define NKV    4
#define HDIM   128
#define BATCH  2
#define SEQ    2048
#define DMODEL 2048
#define NTOK   (BATCH*SEQ)

// ---------------------------------------------------------------------------
// scratch (no cudaMalloc allowed)
// ---------------------------------------------------------------------------
static __device__ float g_q[NTOK * NH * HDIM];
static __device__ float g_k[NTOK * NKV * HDIM];
static __device__ float g_v[NTOK * NKV * HDIM];
static __device__ float g_ctx[NTOK * NH * HDIM];

static __device__ __nv_bfloat16 g_qh[NTOK * NH * HDIM];
static __device__ __nv_bfloat16 g_ql[NTOK * NH * HDIM];
static __device__ __nv_bfloat16 g_kbh[NTOK * NKV * HDIM];
static __device__ __nv_bfloat16 g_kbl[NTOK * NKV * HDIM];
static __device__ __nv_bfloat16 g_vbh[NTOK * NKV * HDIM];
static __device__ __nv_bfloat16 g_vbl[NTOK * NKV * HDIM];

static __device__ __nv_bfloat16 g_xh[NTOK * DMODEL];
static __device__ __nv_bfloat16 g_xl[NTOK * DMODEL];
static __device__ __nv_bfloat16 g_cth[NTOK * DMODEL];
static __device__ __nv_bfloat16 g_ctl[NTOK * DMODEL];
static __device__ __nv_bfloat16 g_wqh[DMODEL * (NH*HDIM)];
static __device__ __nv_bfloat16 g_wql[DMODEL * (NH*HDIM)];
static __device__ __nv_bfloat16 g_wkh[DMODEL * (NKV*HDIM)];
static __device__ __nv_bfloat16 g_wkl[DMODEL * (NKV*HDIM)];
static __device__ __nv_bfloat16 g_wvh[DMODEL * (NKV*HDIM)];
static __device__ __nv_bfloat16 g_wvl[DMODEL * (NKV*HDIM)];
static __device__ __nv_bfloat16 g_woh[DMODEL * DMODEL];
static __device__ __nv_bfloat16 g_wol[DMODEL * DMODEL];

// ---------------------------------------------------------------------------
// helpers
// ---------------------------------------------------------------------------
__device__ __forceinline__ uint32_t smem_u32(const void* p) {
  uint32_t a;
  asm("{ .reg .u64 t; cvta.to.shared.u64 t, %1; cvt.u32.u64 %0, t; }" : "=r"(a) : "l"(p));
  return a;
}

#define LDSM4(R, addr)                                                        \
  asm volatile("ldmatrix.sync.aligned.m8n8.x4.shared.b16 {%0,%1,%2,%3}, [%4];"\
    : "=r"((R)[0]), "=r"((R)[1]), "=r"((R)[2]), "=r"((R)[3]) : "r"(addr))

#define LDSM4T(R, addr)                                                       \
  asm volatile("ldmatrix.sync.aligned.m8n8.x4.trans.shared.b16 {%0,%1,%2,%3}, [%4];"\
    : "=r"((R)[0]), "=r"((R)[1]), "=r"((R)[2]), "=r"((R)[3]) : "r"(addr))

#define MMA16816(D, A, b0v, b1v)                                              \
  asm volatile("mma.sync.aligned.m16n8k16.row.col.f32.bf16.bf16.f32 "         \
    "{%0,%1,%2,%3}, {%4,%5,%6,%7}, {%8,%9}, {%0,%1,%2,%3};"                   \
    : "+f"((D)[0]), "+f"((D)[1]), "+f"((D)[2]), "+f"((D)[3])                  \
    : "r"((A)[0]), "r"((A)[1]), "r"((A)[2]), "r"((A)[3]), "r"(b0v), "r"(b1v))

#define CP_ASYNC16(dst, src) \
  asm volatile("cp.async.cg.shared.global [%0], [%1], 16;" :: "r"(dst), "l"(src))
#define CP_COMMIT() asm volatile("cp.async.commit_group;")

// ---------------------------------------------------------------------------
// split fp32 -> bf16 hi/lo
// ---------------------------------------------------------------------------
__global__ void __launch_bounds__(256) split_kernel(const float* __restrict__ src,
    __nv_bfloat16* __restrict__ hi, __nv_bfloat16* __restrict__ lo, int n) {
  int i = blockIdx.x * 256 + threadIdx.x;
  if (i < n) {
    float v = src[i];
    __nv_bfloat16 h = __float2bfloat16(v);
    hi[i] = h;
    lo[i] = __float2bfloat16(v - __bfloat162float(h));
  }
}

// W [K,N] fp32 -> transposed bf16 hi/lo [N,K]
__global__ void __launch_bounds__(256) wsplit_kernel(const float* __restrict__ W,
    __nv_bfloat16* __restrict__ th, __nv_bfloat16* __restrict__ tl, int K, int N) {
  __shared__ float t[32][33];
  int n0 = blockIdx.x * 32, k0 = blockIdx.y * 32;
  int x = threadIdx.x, y = threadIdx.y;  // 32 x 8
  #pragma unroll
  for (int i = 0; i < 4; i++)
    t[y * 4 + i][x] = W[(size_t)(k0 + y * 4 + i) * N + n0 + x];
  __syncthreads();
  #pragma unroll
  for (int i = 0; i < 4; i++) {
    int n = n0 + y * 4 + i;
    float v = t[x][y * 4 + i];
    __nv_bfloat16 h = __float2bfloat16(v);
    th[(size_t)n * K + k0 + x] = h;
    tl[(size_t)n * K + k0 + x] = __float2bfloat16(v - __bfloat162float(h));
  }
}

// ---------------------------------------------------------------------------
// mma.sync GEMM with bf16x3 split (unchanged from round 3)
// ---------------------------------------------------------------------------
#define GBM 128
#define GBN 128
#define GBK 32
#define RSTRIDE 80
#define TILE_BYTES (128 * RSTRIDE)
#define CH_BYTES (4 * TILE_BYTES)
#define GEMM_SMEM (2 * CH_BYTES)

__global__ void __launch_bounds__(256) gemm3_kernel(
    const __nv_bfloat16* __restrict__ Ah, const __nv_bfloat16* __restrict__ Al,
    const __nv_bfloat16* __restrict__ Bh, const __nv_bfloat16* __restrict__ Bl,
    float* __restrict__ C, int K, int N) {
  extern __shared__ char smem[];
  uint32_t sbase = smem_u32(smem);
  int tid = threadIdx.x;
  int wid = tid >> 5, lane = tid & 31;
  int wm = wid >> 1, wn = wid & 1;
  int bm = blockIdx.y * GBM, bn = blockIdx.x * GBN;
  int nc = K / GBK;

  const __nv_bfloat16* srcs[4] = {Ah, Al, Bh, Bl};
  int rbase[4] = {bm, bm, bn, bn};

  auto load_chunk = [&](int c, int buf) {
    int k0 = c * GBK;
    #pragma unroll
    for (int i = 0; i < 8; i++) {
      int idx = tid + i * 256;
      int t = idx >> 9;
      int r = (idx >> 2) & 127;
      int g = idx & 3;
      uint32_t dst = sbase + buf * CH_BYTES + t * TILE_BYTES + r * RSTRIDE + g * 16;
      const __nv_bfloat16* src = srcs[t] + (size_t)(rbase[t] + r) * K + k0 + g * 8;
      CP_ASYNC16(dst, src);
    }
    CP_COMMIT();
  };

  float acc[2][8][4];
  #pragma unroll
  for (int mi = 0; mi < 2; mi++)
    #pragma unroll
    for (int ni = 0; ni < 8; ni++)
      #pragma unroll
      for (int j = 0; j < 4; j++) acc[mi][ni][j] = 0.f;

  load_chunk(0, 0);
  int lrow = lane & 15, lk8 = (lane >> 4) * 8;

  for (int c = 0; c < nc; c++) {
    if (c + 1 < nc) {
      load_chunk(c + 1, (c + 1) & 1);
      asm volatile("cp.async.wait_group 1;");
    } else {
      asm volatile("cp.async.wait_group 0;");
    }
    __syncthreads();

    uint32_t b0 = sbase + (c & 1) * CH_BYTES;
    uint32_t aH = b0, aL = b0 + TILE_BYTES;
    uint32_t bH = b0 + 2 * TILE_BYTES, bL = b0 + 3 * TILE_BYTES;

    #pragma unroll
    for (int kk = 0; kk < GBK; kk += 16) {
      uint32_t ah[2][4], al[2][4];
      uint32_t aoff = (uint32_t)(wm * 32 + lrow) * RSTRIDE + (kk + lk8) * 2;
      LDSM4(ah[0], aH + aoff);
      LDSM4(ah[1], aH + aoff + 16 * RSTRIDE);
      LDSM4(al[0], aL + aoff);
      LDSM4(al[1], aL + aoff + 16 * RSTRIDE);
      #pragma unroll
      for (int p = 0; p < 4; p++) {
        uint32_t boff = (uint32_t)(wn * 64 + p * 16 + lrow) * RSTRIDE + (kk + lk8) * 2;
        uint32_t h[4], l[4];
        LDSM4(h, bH + boff);
        LDSM4(l, bL + boff);
        #pragma unroll
        for (int mi = 0; mi < 2; mi++) {
          MMA16816(acc[mi][2 * p],     ah[mi], h[0], h[2]);
          MMA16816(acc[mi][2 * p],     ah[mi], l[0], l[2]);
          MMA16816(acc[mi][2 * p],     al[mi], h[0], h[2]);
          MMA16816(acc[mi][2 * p + 1], ah[mi], h[1], h[3]);
          MMA16816(acc[mi][2 * p + 1], ah[mi], l[1], l[3]);
          MMA16816(acc[mi][2 * p + 1], al[mi], h[1], h[3]);
        }
      }
    }
    __syncthreads();
  }

  int gid = lane >> 2, cid = lane & 3;
  #pragma unroll
  for (int mi = 0; mi < 2; mi++)
    #pragma unroll
    for (int ni = 0; ni < 8; ni++) {
      int row = bm + wm * 32 + mi * 16 + gid;
      int col = bn + wn * 64 + ni * 8 + cid * 2;
      float2 v0 = {acc[mi][ni][0], acc[mi][ni][1]};
      float2 v1 = {acc[mi][ni][2], acc[mi][ni][3]};
      *(float2*)(C + (size_t)row * N + col) = v0;
      *(float2*)(C + (size_t)(row + 8) * N + col) = v1;
    }
}

// ---------------------------------------------------------------------------
// RoPE + L2 norm; also emits bf16 hi/lo copies for the MMA attention.
// ---------------------------------------------------------------------------
__global__ void __launch_bounds__(64) rope_norm_kernel() {
  int tok = blockIdx.x;
  int r = blockIdx.y;
  size_t off = (r < NH) ? ((size_t)tok * NH + r) * HDIM
                        : ((size_t)tok * NKV + (r - NH)) * HDIM;
  float* base = (r < NH) ? g_q + off : g_k + off;
  __nv_bfloat16* bh = (r < NH) ? g_qh + off : g_kbh + off;
  __nv_bfloat16* bl = (r < NH) ? g_ql + off : g_kbl + off;
  int pos = tok & (SEQ - 1);
  int i = threadIdx.x;  // pair 0..63
  float t0 = base[2 * i], t1 = base[2 * i + 1];
  float inv = exp2f((float)(2 * i) * (-13.287712379549449f / 128.0f));
  float ang = (float)pos * inv;
  float sn, cs;
  sincosf(ang, &sn, &cs);
  float r0 = t0 * cs - t1 * sn;
  float r1 = t0 * sn + t1 * cs;
  float ss = r0 * r0 + r1 * r1;
  #pragma unroll
  for (int o = 16; o; o >>= 1) ss += __shfl_xor_sync(0xffffffffu, ss, o);
  __shared__ float part[2];
  if ((i & 31) == 0) part[i >> 5] = ss;
  __syncthreads();
  float sc = rsqrtf((part[0] + part[1]) * (1.0f / 128.0f) + 1e-6f);
  float v0 = r0 * sc, v1 = r1 * sc;
  base[2 * i] = v0;
  base[2 * i + 1] = v1;
  __nv_bfloat16 h0 = __float2bfloat16(v0), h1 = __float2bfloat16(v1);
  bh[2 * i] = h0; bh[2 * i + 1] = h1;
  bl[2 * i] = __float2bfloat16(v0 - __bfloat162float(h0));
  bl[2 * i + 1] = __float2bfloat16(v1 - __bfloat162float(h1));
}

// ---------------------------------------------------------------------------
// MMA attention: block = (b, h, 16-query tile). Full score row in smem.
// QK and PV via m16n8k16 bf16 with x3 split. 8 warps; warp = 16-col slice.
// ---------------------------------------------------------------------------
#define SCW 2056                     // floats per padded score row
#define PAD_STR 272                  // bytes per padded bf16 row (128 cols)
#define OFF_SC 0
#define OFF_QH 131584
#define OFF_QL (OFF_QH + 16*PAD_STR)
#define OFF_KH (OFF_QL + 16*PAD_STR)
#define OFF_KL (OFF_KH + 128*PAD_STR)
#define OFF_PH (OFF_KL + 128*PAD_STR)
#define OFF_PL (OFF_PH + 16*PAD_STR)
#define OFF_RED (OFF_PL + 16*PAD_STR)
#define ATTN_SMEM (OFF_RED + 128)

__global__ void __launch_bounds__(256, 1) attn_mma_kernel(
    float* __restrict__ attn_out, int write_attn) {
  extern __shared__ char smc[];
  float* s_scores = (float*)smc;
  float* s_red = (float*)(smc + OFF_RED);  // [0..15]=m, [16..31]=invZ
  uint32_t sb = smem_u32(smc);

  int qb = gridDim.x - 1 - blockIdx.x;
  int h = blockIdx.y, b = blockIdx.z;
  int hk = h >> 2;
  int tid = threadIdx.x, w = tid >> 5, lane = tid & 31;
  int kend = qb * 16 + 16;
  const float SC = 0.08838834764831845f;
  int lrow = lane & 15, lhi = lane >> 4;

  // load Q tile (pre-split bf16): 16 rows x 16 groups of 16B per split
  {
    int r = tid >> 4, g = tid & 15;
    size_t go = ((size_t)(b * SEQ + qb * 16 + r) * NH + h) * HDIM + g * 8;
    *(uint4*)(smc + OFF_QH + r * PAD_STR + g * 16) = *(const uint4*)(g_qh + go);
    *(uint4*)(smc + OFF_QL + r * PAD_STR + g * 16) = *(const uint4*)(g_ql + go);
  }
  __syncthreads();

  // hoist Q fragments
  uint32_t aH[8][4], aL[8][4];
  #pragma unroll
  for (int kk = 0; kk < 8; kk++) {
    uint32_t off = lrow * PAD_STR + kk * 32 + lhi * 16;
    LDSM4(aH[kk], sb + OFF_QH + off);
    LDSM4(aL[kk], sb + OFF_QL + off);
  }

  // ---- phase 1: scores ----
  for (int kc = 0; kc < kend; kc += 128) {
    __syncthreads();
    for (int idx = tid; idx < 128 * 16; idx += 256) {
      int j = idx >> 4, g = idx & 15;
      uint4 vh = {0, 0, 0, 0}, vl = {0, 0, 0, 0};
      if (kc + j < kend) {
        size_t go = ((size_t)(b * SEQ + kc + j) * NKV + hk) * HDIM + g * 8;
        vh = *(const uint4*)(g_kbh + go);
        vl = *(const uint4*)(g_kbl + go);
      }
      *(uint4*)(smc + OFF_KH + j * PAD_STR + g * 16) = vh;
      *(uint4*)(smc + OFF_KL + j * PAD_STR + g * 16) = vl;
    }
    __syncthreads();

    float acc[2][4] = {{0, 0, 0, 0}, {0, 0, 0, 0}};
    int n0 = w * 16;
    #pragma unroll
    for (int kk = 0; kk < 8; kk++) {
      uint32_t off = (n0 + lrow) * PAD_STR + kk * 32 + lhi * 16;
      uint32_t bh[4], bl[4];
      LDSM4(bh, sb + OFF_KH + off);
      LDSM4(bl, sb + OFF_KL + off);
      MMA16816(acc[0], aH[kk], bh[0], bh[2]);
      MMA16816(acc[1], aH[kk], bh[1], bh[3]);
      MMA16816(acc[0], aH[kk], bl[0], bl[2]);
      MMA16816(acc[1], aH[kk], bl[1], bl[3]);
      MMA16816(acc[0], aL[kk], bh[0], bh[2]);
      MMA16816(acc[1], aL[kk], bh[1], bh[3]);
    }
    int r0 = lane >> 2, c0 = (lane & 3) * 2;
    int qs0 = qb * 16;
    #pragma unroll
    for (int nt = 0; nt < 2; nt++) {
      int col = kc + n0 + nt * 8 + c0;
      s_scores[r0 * SCW + col]       = (col     <= qs0 + r0)     ? acc[nt][0] * SC : -1e30f;
      s_scores[r0 * SCW + col + 1]   = (col + 1 <= qs0 + r0)     ? acc[nt][1] * SC : -1e30f;
      s_scores[(r0 + 8) * SCW + col]     = (col     <= qs0 + r0 + 8) ? acc[nt][2] * SC : -1e30f;
      s_scores[(r0 + 8) * SCW + col + 1] = (col + 1 <= qs0 + r0 + 8) ? acc[nt][3] * SC : -1e30f;
    }
  }
  __syncthreads();

  // ---- phase 2: softmax stats ----
  {
    int qi = tid >> 4, r = tid & 15;
    float m = -1e30f;
    for (int j = r; j < kend; j += 16) m = fmaxf(m, s_scores[qi * SCW + j]);
    #pragma unroll
    for (int o = 8; o; o >>= 1) m = fmaxf(m, __shfl_xor_sync(0xffffffffu, m, o));
    float s = 0.f;
    for (int j = r; j < kend; j += 16) s += __expf(s_scores[qi * SCW + j] - m);
    #pragma unroll
    for (int o = 8; o; o >>= 1) s += __shfl_xor_sync(0xffffffffu, s, o);
    if (r == 0) { s_red[qi] = m; s_red[16 + qi] = 1.0f / s; }
  }
  __syncthreads();

  // ---- phase 2b: write attn probs (full rows incl. zeros) ----
  if (write_attn) {
    float* ab = attn_out + ((size_t)(b * NH + h) * SEQ + (size_t)qb * 16) * SEQ;
    for (int idx = tid; idx < 16 * 512; idx += 256) {
      int qi = idx >> 9, j4 = (idx & 511) * 4;
      float m = s_red[qi], inv = s_red[16 + qi];
      float4 p = {0, 0, 0, 0};
      if (j4 < kend) {
        p.x = __expf(s_scores[qi * SCW + j4] - m) * inv;
        if (j4 + 1 < kend) p.y = __expf(s_scores[qi * SCW + j4 + 1] - m) * inv;
        if (j4 + 2 < kend) p.z = __expf(s_scores[qi * SCW + j4 + 2] - m) * inv;
        if (j4 + 3 < kend) p.w = __expf(s_scores[qi * SCW + j4 + 3] - m) * inv;
      }
      *(float4*)(ab + (size_t)qi * SEQ + j4) = p;
    }
  }

  // ---- phase 3: AV ----
  float oacc[2][4] = {{0, 0, 0, 0}, {0, 0, 0, 0}};
  for (int kc = 0; kc < kend; kc += 128) {
    __syncthreads();
    // V chunk (zero-filled beyond kend)
    for (int idx = tid; idx < 128 * 16; idx += 256) {
      int j = idx >> 4, g = idx & 15;
      uint4 vh = {0, 0, 0, 0}, vl = {0, 0, 0, 0};
      if (kc + j < kend) {
        size_t go = ((size_t)(b * SEQ + kc + j) * NKV + hk) * HDIM + g * 8;
        vh = *(const uint4*)(g_vbh + go);
        vl = *(const uint4*)(g_vbl + go);
      }
      *(uint4*)(smc + OFF_KH + j * PAD_STR + g * 16) = vh;
      *(uint4*)(smc + OFF_KL + j * PAD_STR + g * 16) = vl;
    }
    // P staging: 16 rows x 64 col-pairs
    for (int idx = tid; idx < 16 * 64; idx += 256) {
      int r = idx >> 6, c2 = (idx & 63) * 2;
      float m = s_red[r], inv = s_red[16 + r];
      float p0 = 0.f, p1 = 0.f;
      if (kc + c2 < kend)     p0 = __expf(s_scores[r * SCW + kc + c2] - m) * inv;
      if (kc + c2 + 1 < kend) p1 = __expf(s_scores[r * SCW + kc + c2 + 1] - m) * inv;
      __nv_bfloat16 h0 = __float2bfloat16(p0), h1 = __float2bfloat16(p1);
      __nv_bfloat162 hh; hh.x = h0; hh.y = h1;
      __nv_bfloat162 ll;
      ll.x = __float2bfloat16(p0 - __bfloat162float(h0));
      ll.y = __float2bfloat16(p1 - __bfloat162float(h1));
      *(__nv_bfloat162*)(smc + OFF_PH + r * PAD_STR + c2 * 2) = hh;
      *(__nv_bfloat162*)(smc + OFF_PL + r * PAD_STR + c2 * 2) = ll;
    }
    __syncthreads();

    #pragma unroll
    for (int kk = 0; kk < 8; kk++) {
      uint32_t pOff = lrow * PAD_STR + kk * 32 + lhi * 16;
      uint32_t ph[4], pl[4];
      LDSM4(ph, sb + OFF_PH + pOff);
      LDSM4(pl, sb + OFF_PL + pOff);
      uint32_t vOff = (kk * 16 + lrow) * PAD_STR + w * 32 + lhi * 16;
      uint32_t vh[4], vl[4];
      LDSM4T(vh, sb + OFF_KH + vOff);
      LDSM4T(vl, sb + OFF_KL + vOff);
      MMA16816(oacc[0], ph, vh[0], vh[1]);
      MMA16816(oacc[1], ph, vh[2], vh[3]);
      MMA16816(oacc[0], ph, vl[0], vl[1]);
      MMA16816(oacc[1], ph, vl[2], vl[3]);
      MMA16816(oacc[0], pl, vh[0], vh[1]);
      MMA16816(oacc[1], pl, vh[2], vh[3]);
    }
  }

  // epilogue: ctx [tok, H, HD]
  {
    int r0 = lane >> 2, c0 = (lane & 3) * 2;
    #pragma unroll
    for (int nt = 0; nt < 2; nt++) {
      int col = w * 16 + nt * 8 + c0;
      float* cb0 = g_ctx + ((size_t)(b * SEQ + qb * 16 + r0) * NH + h) * HDIM + col;
      float* cb1 = g_ctx + ((size_t)(b * SEQ + qb * 16 + r0 + 8) * NH + h) * HDIM + col;
      *(float2*)cb0 = make_float2(oacc[nt][0], oacc[nt][1]);
      *(float2*)cb1 = make_float2(oacc[nt][2], oacc[nt][3]);
    }
  }
}

// ---------------------------------------------------------------------------
extern "C" void kernel_launch(void* const* d_in, const int* in_sizes, int n_in,
                              void* d_out, int out_size) {
  const float* x  = (const float*)d_in[0];
  const float* Wq = (const float*)d_in[1];
  const float* Wk = (const float*)d_in[2];
  const float* Wv = (const float*)d_in[3];
  const float* Wo = (const float*)d_in[4];
  float* out = (float*)d_out;
  float* attn = out + (size_t)NTOK * DMODEL;
  long long need = (long long)NTOK * DMODEL + (long long)BATCH * NH * SEQ * SEQ;
  int write_attn = ((long long)out_size >= need) ? 1 : 0;

  float *gq, *gk, *gv, *gctx;
  __nv_bfloat16 *xh, *xl, *cth, *ctl, *vbh, *vbl;
  __nv_bfloat16 *wqh, *wql, *wkh, *wkl, *wvh, *wvl, *woh, *wol;
  cudaGetSymbolAddress((void**)&gq, g_q);
  cudaGetSymbolAddress((void**)&gk, g_k);
  cudaGetSymbolAddress((void**)&gv, g_v);
  cudaGetSymbolAddress((void**)&gctx, g_ctx);
  cudaGetSymbolAddress((void**)&xh, g_xh);
  cudaGetSymbolAddress((void**)&xl, g_xl);
  cudaGetSymbolAddress((void**)&cth, g_cth);
  cudaGetSymbolAddress((void**)&ctl, g_ctl);
  cudaGetSymbolAddress((void**)&vbh, g_vbh);
  cudaGetSymbolAddress((void**)&vbl, g_vbl);
  cudaGetSymbolAddress((void**)&wqh, g_wqh);
  cudaGetSymbolAddress((void**)&wql, g_wql);
  cudaGetSymbolAddress((void**)&wkh, g_wkh);
  cudaGetSymbolAddress((void**)&wkl, g_wkl);
  cudaGetSymbolAddress((void**)&wvh, g_wvh);
  cudaGetSymbolAddress((void**)&wvl, g_wvl);
  cudaGetSymbolAddress((void**)&woh, g_woh);
  cudaGetSymbolAddress((void**)&wol, g_wol);

  cudaFuncSetAttribute(gemm3_kernel, cudaFuncAttributeMaxDynamicSharedMemorySize,
                       GEMM_SMEM);
  cudaFuncSetAttribute(attn_mma_kernel, cudaFuncAttributeMaxDynamicSharedMemorySize,
                       ATTN_SMEM);

  // prep
  {
    int n = NTOK * DMODEL;
    split_kernel<<<(n + 255) / 256, 256>>>(x, xh, xl, n);
  }
  wsplit_kernel<<<dim3((NH*HDIM)/32, DMODEL/32), dim3(32, 8)>>>(Wq, wqh, wql, DMODEL, NH*HDIM);
  wsplit_kernel<<<dim3((NKV*HDIM)/32, DMODEL/32), dim3(32, 8)>>>(Wk, wkh, wkl, DMODEL, NKV*HDIM);
  wsplit_kernel<<<dim3((NKV*HDIM)/32, DMODEL/32), dim3(32, 8)>>>(Wv, wvh, wvl, DMODEL, NKV*HDIM);
  wsplit_kernel<<<dim3(DMODEL/32, DMODEL/32), dim3(32, 8)>>>(Wo, woh, wol, DMODEL, DMODEL);

  // QKV projections
  gemm3_kernel<<<dim3((NH*HDIM)/GBN, NTOK/GBM), 256, GEMM_SMEM>>>(xh, xl, wqh, wql, gq, DMODEL, NH*HDIM);
  gemm3_kernel<<<dim3((NKV*HDIM)/GBN, NTOK/GBM), 256, GEMM_SMEM>>>(xh, xl, wkh, wkl, gk, DMODEL, NKV*HDIM);
  gemm3_kernel<<<dim3((NKV*HDIM)/GBN, NTOK/GBM), 256, GEMM_SMEM>>>(xh, xl, wvh, wvl, gv, DMODEL, NKV*HDIM);

  // RoPE + l2norm (also emits split bf16 q/k); split v
  rope_norm_kernel<<<dim3(NTOK, NH + NKV), 64>>>();
  {
    int n = NTOK * NKV * HDIM;
    split_kernel<<<(n + 255) / 256, 256>>>(gv, vbh, vbl, n);
  }

  // attention
  attn_mma_kernel<<<dim3(SEQ / 16, NH, BATCH), 256, ATTN_SMEM>>>(attn, write_attn);

  // output projection
  {
    int n = NTOK * DMODEL;
    split_kernel<<<(n + 255) / 256, 256>>>(gctx, cth, ctl, n);
  }
  gemm3_kernel<<<dim3(DMODEL/GBN, NTOK/GBM), 256, GEMM_SMEM>>>(cth, ctl, woh, wol, out, DMODEL, DMODEL);
}

// round 5
// speedup vs baseline: 2.1432x; 1.0095x over previous
#include <cuda_runtime.h>
#include <cuda_bf16.h>
#include <math.h>
#include <stdint.h>

#define NH     16
#define NKV    4
#define HDIM   128
#define BATCH  2
#define SEQ    2048
#define DMODEL 2048
#define NTOK   (BATCH*SEQ)

// ---------------------------------------------------------------------------
// scratch
// ---------------------------------------------------------------------------
static __device__ float g_q[NTOK * NH * HDIM];
static __device__ float g_k[NTOK * NKV * HDIM];

static __device__ __nv_bfloat16 g_qh[NTOK * NH * HDIM];
static __device__ __nv_bfloat16 g_ql[NTOK * NH * HDIM];
static __device__ __nv_bfloat16 g_kbh[NTOK * NKV * HDIM];
static __device__ __nv_bfloat16 g_kbl[NTOK * NKV * HDIM];
static __device__ __nv_bfloat16 g_vbh[NTOK * NKV * HDIM];
static __device__ __nv_bfloat16 g_vbl[NTOK * NKV * HDIM];

static __device__ __nv_bfloat16 g_xh[NTOK * DMODEL];
static __device__ __nv_bfloat16 g_xl[NTOK * DMODEL];
static __device__ __nv_bfloat16 g_cth[NTOK * DMODEL];
static __device__ __nv_bfloat16 g_ctl[NTOK * DMODEL];
static __device__ __nv_bfloat16 g_wqh[DMODEL * (NH*HDIM)];
static __device__ __nv_bfloat16 g_wql[DMODEL * (NH*HDIM)];
static __device__ __nv_bfloat16 g_wkh[DMODEL * (NKV*HDIM)];
static __device__ __nv_bfloat16 g_wkl[DMODEL * (NKV*HDIM)];
static __device__ __nv_bfloat16 g_wvh[DMODEL * (NKV*HDIM)];
static __device__ __nv_bfloat16 g_wvl[DMODEL * (NKV*HDIM)];
static __device__ __nv_bfloat16 g_woh[DMODEL * DMODEL];
static __device__ __nv_bfloat16 g_wol[DMODEL * DMODEL];

// ---------------------------------------------------------------------------
// helpers
// ---------------------------------------------------------------------------
__device__ __forceinline__ uint32_t smem_u32(const void* p) {
  uint32_t a;
  asm("{ .reg .u64 t; cvta.to.shared.u64 t, %1; cvt.u32.u64 %0, t; }" : "=r"(a) : "l"(p));
  return a;
}

#define LDSM4(R, addr)                                                        \
  asm volatile("ldmatrix.sync.aligned.m8n8.x4.shared.b16 {%0,%1,%2,%3}, [%4];"\
    : "=r"((R)[0]), "=r"((R)[1]), "=r"((R)[2]), "=r"((R)[3]) : "r"(addr))

#define LDSM4T(R, addr)                                                       \
  asm volatile("ldmatrix.sync.aligned.m8n8.x4.trans.shared.b16 {%0,%1,%2,%3}, [%4];"\
    : "=r"((R)[0]), "=r"((R)[1]), "=r"((R)[2]), "=r"((R)[3]) : "r"(addr))

#define MMA16816(D, A, b0v, b1v)                                              \
  asm volatile("mma.sync.aligned.m16n8k16.row.col.f32.bf16.bf16.f32 "         \
    "{%0,%1,%2,%3}, {%4,%5,%6,%7}, {%8,%9}, {%0,%1,%2,%3};"                   \
    : "+f"((D)[0]), "+f"((D)[1]), "+f"((D)[2]), "+f"((D)[3])                  \
    : "r"((A)[0]), "r"((A)[1]), "r"((A)[2]), "r"((A)[3]), "r"(b0v), "r"(b1v))

#define CP_ASYNC16(dst, src) \
  asm volatile("cp.async.cg.shared.global [%0], [%1], 16;" :: "r"(dst), "l"(src))
#define CP_COMMIT() asm volatile("cp.async.commit_group;")

// ---------------------------------------------------------------------------
// split fp32 -> bf16 hi/lo
// ---------------------------------------------------------------------------
__global__ void __launch_bounds__(256) split_kernel(const float* __restrict__ src,
    __nv_bfloat16* __restrict__ hi, __nv_bfloat16* __restrict__ lo, int n) {
  int i = blockIdx.x * 256 + threadIdx.x;
  if (i < n) {
    float v = src[i];
    __nv_bfloat16 h = __float2bfloat16(v);
    hi[i] = h;
    lo[i] = __float2bfloat16(v - __bfloat162float(h));
  }
}

// W [K,N] fp32 -> transposed bf16 hi/lo [N,K]
__global__ void __launch_bounds__(256) wsplit_kernel(const float* __restrict__ W,
    __nv_bfloat16* __restrict__ th, __nv_bfloat16* __restrict__ tl, int K, int N) {
  __shared__ float t[32][33];
  int n0 = blockIdx.x * 32, k0 = blockIdx.y * 32;
  int x = threadIdx.x, y = threadIdx.y;  // 32 x 8
  #pragma unroll
  for (int i = 0; i < 4; i++)
    t[y * 4 + i][x] = W[(size_t)(k0 + y * 4 + i) * N + n0 + x];
  __syncthreads();
  #pragma unroll
  for (int i = 0; i < 4; i++) {
    int n = n0 + y * 4 + i;
    float v = t[x][y * 4 + i];
    __nv_bfloat16 h = __float2bfloat16(v);
    th[(size_t)n * K + k0 + x] = h;
    tl[(size_t)n * K + k0 + x] = __float2bfloat16(v - __bfloat162float(h));
  }
}

// ---------------------------------------------------------------------------
// Multistage mma.sync GEMM, bf16x3 split: C = A @ B^T (B stored [N,K]).
// 128x128 CTA tile, BK=32, 4 stages, ONE barrier per chunk.
// Epilogue: fp32 (Cf) or direct bf16 hi/lo split (Ch/Cl).
// ---------------------------------------------------------------------------
#define GBM 128
#define GBN 128
#define GBK 32
#define RSTRIDE 80
#define TILE_BYTES (128 * RSTRIDE)     // 10240
#define STG_BYTES (4 * TILE_BYTES)     // 40960 per stage
#define GEMM_SMEM (4 * STG_BYTES)      // 163840

__global__ void __launch_bounds__(256) gemm3_kernel(
    const __nv_bfloat16* __restrict__ Ah, const __nv_bfloat16* __restrict__ Al,
    const __nv_bfloat16* __restrict__ Bh, const __nv_bfloat16* __restrict__ Bl,
    float* __restrict__ Cf, __nv_bfloat16* __restrict__ Ch,
    __nv_bfloat16* __restrict__ Cl, int K, int N) {
  extern __shared__ char smem[];
  uint32_t sbase = smem_u32(smem);
  int tid = threadIdx.x;
  int wid = tid >> 5, lane = tid & 31;
  int wm = wid >> 1, wn = wid & 1;
  int bm = blockIdx.y * GBM, bn = blockIdx.x * GBN;
  int nc = K / GBK;

  const __nv_bfloat16* srcs[4] = {Ah, Al, Bh, Bl};
  int rbase[4] = {bm, bm, bn, bn};

  auto load_chunk = [&](int c, int buf) {
    int k0 = c * GBK;
    #pragma unroll
    for (int i = 0; i < 8; i++) {
      int idx = tid + i * 256;
      int t = i >> 1;                  // tile index (compile-time per i)
      int r = (idx >> 2) & 127;
      int g = idx & 3;
      uint32_t dst = sbase + buf * STG_BYTES + t * TILE_BYTES + r * RSTRIDE + g * 16;
      const __nv_bfloat16* src = srcs[t] + (size_t)(rbase[t] + r) * K + k0 + g * 8;
      CP_ASYNC16(dst, src);
    }
    CP_COMMIT();
  };

  float acc[2][8][4];
  #pragma unroll
  for (int mi = 0; mi < 2; mi++)
    #pragma unroll
    for (int ni = 0; ni < 8; ni++)
      #pragma unroll
      for (int j = 0; j < 4; j++) acc[mi][ni][j] = 0.f;

  // prologue: 3 chunks in flight
  load_chunk(0, 0);
  load_chunk(1, 1);
  load_chunk(2, 2);

  int lrow = lane & 15, lk8 = (lane >> 4) * 8;

  for (int c = 0; c < nc; c++) {
    asm volatile("cp.async.wait_group 2;");
    __syncthreads();
    if (c + 3 < nc) load_chunk(c + 3, (c + 3) & 3);
    else CP_COMMIT();   // keep group accounting uniform

    uint32_t b0 = sbase + (c & 3) * STG_BYTES;
    uint32_t aH = b0, aL = b0 + TILE_BYTES;
    uint32_t bH = b0 + 2 * TILE_BYTES, bL = b0 + 3 * TILE_BYTES;

    #pragma unroll
    for (int kk = 0; kk < GBK; kk += 16) {
      uint32_t ah[2][4], al[2][4];
      uint32_t aoff = (uint32_t)(wm * 32 + lrow) * RSTRIDE + (kk + lk8) * 2;
      LDSM4(ah[0], aH + aoff);
      LDSM4(ah[1], aH + aoff + 16 * RSTRIDE);
      LDSM4(al[0], aL + aoff);
      LDSM4(al[1], aL + aoff + 16 * RSTRIDE);
      #pragma unroll
      for (int p = 0; p < 4; p++) {
        uint32_t boff = (uint32_t)(wn * 64 + p * 16 + lrow) * RSTRIDE + (kk + lk8) * 2;
        uint32_t h[4], l[4];
        LDSM4(h, bH + boff);
        LDSM4(l, bL + boff);
        #pragma unroll
        for (int mi = 0; mi < 2; mi++) {
          MMA16816(acc[mi][2 * p],     ah[mi], h[0], h[2]);
          MMA16816(acc[mi][2 * p],     ah[mi], l[0], l[2]);
          MMA16816(acc[mi][2 * p],     al[mi], h[0], h[2]);
          MMA16816(acc[mi][2 * p + 1], ah[mi], h[1], h[3]);
          MMA16816(acc[mi][2 * p + 1], ah[mi], l[1], l[3]);
          MMA16816(acc[mi][2 * p + 1], al[mi], h[1], h[3]);
        }
      }
    }
  }

  int gid = lane >> 2, cid = lane & 3;
  if (Cf) {
    #pragma unroll
    for (int mi = 0; mi < 2; mi++)
      #pragma unroll
      for (int ni = 0; ni < 8; ni++) {
        int row = bm + wm * 32 + mi * 16 + gid;
        int col = bn + wn * 64 + ni * 8 + cid * 2;
        *(float2*)(Cf + (size_t)row * N + col) =
            make_float2(acc[mi][ni][0], acc[mi][ni][1]);
        *(float2*)(Cf + (size_t)(row + 8) * N + col) =
            make_float2(acc[mi][ni][2], acc[mi][ni][3]);
      }
  } else {
    #pragma unroll
    for (int mi = 0; mi < 2; mi++)
      #pragma unroll
      for (int ni = 0; ni < 8; ni++) {
        int row = bm + wm * 32 + mi * 16 + gid;
        int col = bn + wn * 64 + ni * 8 + cid * 2;
        #pragma unroll
        for (int half = 0; half < 2; half++) {
          float v0 = acc[mi][ni][2 * half], v1 = acc[mi][ni][2 * half + 1];
          __nv_bfloat16 h0 = __float2bfloat16(v0), h1 = __float2bfloat16(v1);
          __nv_bfloat162 hh; hh.x = h0; hh.y = h1;
          __nv_bfloat162 ll;
          ll.x = __float2bfloat16(v0 - __bfloat162float(h0));
          ll.y = __float2bfloat16(v1 - __bfloat162float(h1));
          size_t o = (size_t)(row + half * 8) * N + col;
          *(__nv_bfloat162*)(Ch + o) = hh;
          *(__nv_bfloat162*)(Cl + o) = ll;
        }
      }
  }
}

// ---------------------------------------------------------------------------
// RoPE + L2 norm: reads fp32 q/k, writes split bf16 only.
// ---------------------------------------------------------------------------
__global__ void __launch_bounds__(64) rope_norm_kernel() {
  int tok = blockIdx.x;
  int r = blockIdx.y;
  size_t off = (r < NH) ? ((size_t)tok * NH + r) * HDIM
                        : ((size_t)tok * NKV + (r - NH)) * HDIM;
  const float* base = (r < NH) ? g_q + off : g_k + off;
  __nv_bfloat16* bh = (r < NH) ? g_qh + off : g_kbh + off;
  __nv_bfloat16* bl = (r < NH) ? g_ql + off : g_kbl + off;
  int pos = tok & (SEQ - 1);
  int i = threadIdx.x;  // pair 0..63
  float t0 = base[2 * i], t1 = base[2 * i + 1];
  float inv = exp2f((float)(2 * i) * (-13.287712379549449f / 128.0f));
  float ang = (float)pos * inv;
  float sn, cs;
  sincosf(ang, &sn, &cs);
  float r0 = t0 * cs - t1 * sn;
  float r1 = t0 * sn + t1 * cs;
  float ss = r0 * r0 + r1 * r1;
  #pragma unroll
  for (int o = 16; o; o >>= 1) ss += __shfl_xor_sync(0xffffffffu, ss, o);
  __shared__ float part[2];
  if ((i & 31) == 0) part[i >> 5] = ss;
  __syncthreads();
  float sc = rsqrtf((part[0] + part[1]) * (1.0f / 128.0f) + 1e-6f);
  float v0 = r0 * sc, v1 = r1 * sc;
  __nv_bfloat16 h0 = __float2bfloat16(v0), h1 = __float2bfloat16(v1);
  bh[2 * i] = h0; bh[2 * i + 1] = h1;
  bl[2 * i] = __float2bfloat16(v0 - __bfloat162float(h0));
  bl[2 * i + 1] = __float2bfloat16(v1 - __bfloat162float(h1));
}

// ---------------------------------------------------------------------------
// MMA attention (as round 4), epilogue writes split bf16 ctx directly.
// ---------------------------------------------------------------------------
#define SCW 2056
#define PAD_STR 272
#define OFF_QH 131584
#define OFF_QL (OFF_QH + 16*PAD_STR)
#define OFF_KH (OFF_QL + 16*PAD_STR)
#define OFF_KL (OFF_KH + 128*PAD_STR)
#define OFF_PH (OFF_KL + 128*PAD_STR)
#define OFF_PL (OFF_PH + 16*PAD_STR)
#define OFF_RED (OFF_PL + 16*PAD_STR)
#define ATTN_SMEM (OFF_RED + 128)

__global__ void __launch_bounds__(256, 1) attn_mma_kernel(
    float* __restrict__ attn_out, int write_attn) {
  extern __shared__ char smc[];
  float* s_scores = (float*)smc;
  float* s_red = (float*)(smc + OFF_RED);
  uint32_t sb = smem_u32(smc);

  int qb = gridDim.x - 1 - blockIdx.x;
  int h = blockIdx.y, b = blockIdx.z;
  int hk = h >> 2;
  int tid = threadIdx.x, w = tid >> 5, lane = tid & 31;
  int kend = qb * 16 + 16;
  const float SC = 0.08838834764831845f;
  int lrow = lane & 15, lhi = lane >> 4;

  {
    int r = tid >> 4, g = tid & 15;
    size_t go = ((size_t)(b * SEQ + qb * 16 + r) * NH + h) * HDIM + g * 8;
    *(uint4*)(smc + OFF_QH + r * PAD_STR + g * 16) = *(const uint4*)(g_qh + go);
    *(uint4*)(smc + OFF_QL + r * PAD_STR + g * 16) = *(const uint4*)(g_ql + go);
  }
  __syncthreads();

  uint32_t aH[8][4], aL[8][4];
  #pragma unroll
  for (int kk = 0; kk < 8; kk++) {
    uint32_t off = lrow * PAD_STR + kk * 32 + lhi * 16;
    LDSM4(aH[kk], sb + OFF_QH + off);
    LDSM4(aL[kk], sb + OFF_QL + off);
  }

  // ---- scores ----
  for (int kc = 0; kc < kend; kc += 128) {
    __syncthreads();
    for (int idx = tid; idx < 128 * 16; idx += 256) {
      int j = idx >> 4, g = idx & 15;
      uint4 vh = {0, 0, 0, 0}, vl = {0, 0, 0, 0};
      if (kc + j < kend) {
        size_t go = ((size_t)(b * SEQ + kc + j) * NKV + hk) * HDIM + g * 8;
        vh = *(const uint4*)(g_kbh + go);
        vl = *(const uint4*)(g_kbl + go);
      }
      *(uint4*)(smc + OFF_KH + j * PAD_STR + g * 16) = vh;
      *(uint4*)(smc + OFF_KL + j * PAD_STR + g * 16) = vl;
    }
    __syncthreads();

    float acc[2][4] = {{0, 0, 0, 0}, {0, 0, 0, 0}};
    int n0 = w * 16;
    #pragma unroll
    for (int kk = 0; kk < 8; kk++) {
      uint32_t off = (n0 + lrow) * PAD_STR + kk * 32 + lhi * 16;
      uint32_t bh[4], bl[4];
      LDSM4(bh, sb + OFF_KH + off);
      LDSM4(bl, sb + OFF_KL + off);
      MMA16816(acc[0], aH[kk], bh[0], bh[2]);
      MMA16816(acc[1], aH[kk], bh[1], bh[3]);
      MMA16816(acc[0], aH[kk], bl[0], bl[2]);
      MMA16816(acc[1], aH[kk], bl[1], bl[3]);
      MMA16816(acc[0], aL[kk], bh[0], bh[2]);
      MMA16816(acc[1], aL[kk], bh[1], bh[3]);
    }
    int r0 = lane >> 2, c0 = (lane & 3) * 2;
    int qs0 = qb * 16;
    #pragma unroll
    for (int nt = 0; nt < 2; nt++) {
      int col = kc + n0 + nt * 8 + c0;
      s_scores[r0 * SCW + col]       = (col     <= qs0 + r0)     ? acc[nt][0] * SC : -1e30f;
      s_scores[r0 * SCW + col + 1]   = (col + 1 <= qs0 + r0)     ? acc[nt][1] * SC : -1e30f;
      s_scores[(r0 + 8) * SCW + col]     = (col     <= qs0 + r0 + 8) ? acc[nt][2] * SC : -1e30f;
      s_scores[(r0 + 8) * SCW + col + 1] = (col + 1 <= qs0 + r0 + 8) ? acc[nt][3] * SC : -1e30f;
    }
  }
  __syncthreads();

  // ---- softmax stats ----
  {
    int qi = tid >> 4, r = tid & 15;
    float m = -1e30f;
    for (int j = r; j < kend; j += 16) m = fmaxf(m, s_scores[qi * SCW + j]);
    #pragma unroll
    for (int o = 8; o; o >>= 1) m = fmaxf(m, __shfl_xor_sync(0xffffffffu, m, o));
    float s = 0.f;
    for (int j = r; j < kend; j += 16) s += __expf(s_scores[qi * SCW + j] - m);
    #pragma unroll
    for (int o = 8; o; o >>= 1) s += __shfl_xor_sync(0xffffffffu, s, o);
    if (r == 0) { s_red[qi] = m; s_red[16 + qi] = 1.0f / s; }
  }
  __syncthreads();

  // ---- attn prob output ----
  if (write_attn) {
    float* ab = attn_out + ((size_t)(b * NH + h) * SEQ + (size_t)qb * 16) * SEQ;
    for (int idx = tid; idx < 16 * 512; idx += 256) {
      int qi = idx >> 9, j4 = (idx & 511) * 4;
      float m = s_red[qi], inv = s_red[16 + qi];
      float4 p = {0, 0, 0, 0};
      if (j4 < kend) {
        p.x = __expf(s_scores[qi * SCW + j4] - m) * inv;
        if (j4 + 1 < kend) p.y = __expf(s_scores[qi * SCW + j4 + 1] - m) * inv;
        if (j4 + 2 < kend) p.z = __expf(s_scores[qi * SCW + j4 + 2] - m) * inv;
        if (j4 + 3 < kend) p.w = __expf(s_scores[qi * SCW + j4 + 3] - m) * inv;
      }
      *(float4*)(ab + (size_t)qi * SEQ + j4) = p;
    }
  }

  // ---- AV ----
  float oacc[2][4] = {{0, 0, 0, 0}, {0, 0, 0, 0}};
  for (int kc = 0; kc < kend; kc += 128) {
    __syncthreads();
    for (int idx = tid; idx < 128 * 16; idx += 256) {
      int j = idx >> 4, g = idx & 15;
      uint4 vh = {0, 0, 0, 0}, vl = {0, 0, 0, 0};
      if (kc + j < kend) {
        size_t go = ((size_t)(b * SEQ + kc + j) * NKV + hk) * HDIM + g * 8;
        vh = *(const uint4*)(g_vbh + go);
        vl = *(const uint4*)(g_vbl + go);
      }
      *(uint4*)(smc + OFF_KH + j * PAD_STR + g * 16) = vh;
      *(uint4*)(smc + OFF_KL + j * PAD_STR + g * 16) = vl;
    }
    for (int idx = tid; idx < 16 * 64; idx += 256) {
      int r = idx >> 6, c2 = (idx & 63) * 2;
      float m = s_red[r], inv = s_red[16 + r];
      float p0 = 0.f, p1 = 0.f;
      if (kc + c2 < kend)     p0 = __expf(s_scores[r * SCW + kc + c2] - m) * inv;
      if (kc + c2 + 1 < kend) p1 = __expf(s_scores[r * SCW + kc + c2 + 1] - m) * inv;
      __nv_bfloat16 h0 = __float2bfloat16(p0), h1 = __float2bfloat16(p1);
      __nv_bfloat162 hh; hh.x = h0; hh.y = h1;
      __nv_bfloat162 ll;
      ll.x = __float2bfloat16(p0 - __bfloat162float(h0));
      ll.y = __float2bfloat16(p1 - __bfloat162float(h1));
      *(__nv_bfloat162*)(smc + OFF_PH + r * PAD_STR + c2 * 2) = hh;
      *(__nv_bfloat162*)(smc + OFF_PL + r * PAD_STR + c2 * 2) = ll;
    }
    __syncthreads();

    #pragma unroll
    for (int kk = 0; kk < 8; kk++) {
      uint32_t pOff = lrow * PAD_STR + kk * 32 + lhi * 16;
      uint32_t ph[4], pl[4];
      LDSM4(ph, sb + OFF_PH + pOff);
      LDSM4(pl, sb + OFF_PL + pOff);
      uint32_t vOff = (kk * 16 + lrow) * PAD_STR + w * 32 + lhi * 16;
      uint32_t vh[4], vl[4];
      LDSM4T(vh, sb + OFF_KH + vOff);
      LDSM4T(vl, sb + OFF_KL + vOff);
      MMA16816(oacc[0], ph, vh[0], vh[1]);
      MMA16816(oacc[1], ph, vh[2], vh[3]);
      MMA16816(oacc[0], ph, vl[0], vl[1]);
      MMA16816(oacc[1], ph, vl[2], vl[3]);
      MMA16816(oacc[0], pl, vh[0], vh[1]);
      MMA16816(oacc[1], pl, vh[2], vh[3]);
    }
  }

  // epilogue: split ctx bf16 [tok, H*HD]
  {
    int r0 = lane >> 2, c0 = (lane & 3) * 2;
    #pragma unroll
    for (int nt = 0; nt < 2; nt++) {
      int col = w * 16 + nt * 8 + c0;
      #pragma unroll
      for (int half = 0; half < 2; half++) {
        float v0 = oacc[nt][2 * half], v1 = oacc[nt][2 * half + 1];
        __nv_bfloat16 h0 = __float2bfloat16(v0), h1 = __float2bfloat16(v1);
        __nv_bfloat162 hh; hh.x = h0; hh.y = h1;
        __nv_bfloat162 ll;
        ll.x = __float2bfloat16(v0 - __bfloat162float(h0));
        ll.y = __float2bfloat16(v1 - __bfloat162float(h1));
        size_t o = ((size_t)(b * SEQ + qb * 16 + r0 + half * 8)) * DMODEL
                 + h * HDIM + col;
        *(__nv_bfloat162*)(g_cth + o) = hh;
        *(__nv_bfloat162*)(g_ctl + o) = ll;
      }
    }
  }
}

// ---------------------------------------------------------------------------
extern "C" void kernel_launch(void* const* d_in, const int* in_sizes, int n_in,
                              void* d_out, int out_size) {
  const float* x  = (const float*)d_in[0];
  const float* Wq = (const float*)d_in[1];
  const float* Wk = (const float*)d_in[2];
  const float* Wv = (const float*)d_in[3];
  const float* Wo = (const float*)d_in[4];
  float* out = (float*)d_out;
  float* attn = out + (size_t)NTOK * DMODEL;
  long long need = (long long)NTOK * DMODEL + (long long)BATCH * NH * SEQ * SEQ;
  int write_attn = ((long long)out_size >= need) ? 1 : 0;

  float *gq, *gk;
  __nv_bfloat16 *xh, *xl, *cth, *ctl, *vbh, *vbl;
  __nv_bfloat16 *wqh, *wql, *wkh, *wkl, *wvh, *wvl, *woh, *wol;
  cudaGetSymbolAddress((void**)&gq, g_q);
  cudaGetSymbolAddress((void**)&gk, g_k);
  cudaGetSymbolAddress((void**)&xh, g_xh);
  cudaGetSymbolAddress((void**)&xl, g_xl);
  cudaGetSymbolAddress((void**)&cth, g_cth);
  cudaGetSymbolAddress((void**)&ctl, g_ctl);
  cudaGetSymbolAddress((void**)&vbh, g_vbh);
  cudaGetSymbolAddress((void**)&vbl, g_vbl);
  cudaGetSymbolAddress((void**)&wqh, g_wqh);
  cudaGetSymbolAddress((void**)&wql, g_wql);
  cudaGetSymbolAddress((void**)&wkh, g_wkh);
  cudaGetSymbolAddress((void**)&wkl, g_wkl);
  cudaGetSymbolAddress((void**)&wvh, g_wvh);
  cudaGetSymbolAddress((void**)&wvl, g_wvl);
  cudaGetSymbolAddress((void**)&woh, g_woh);
  cudaGetSymbolAddress((void**)&wol, g_wol);

  cudaFuncSetAttribute(gemm3_kernel, cudaFuncAttributeMaxDynamicSharedMemorySize,
                       GEMM_SMEM);
  cudaFuncSetAttribute(attn_mma_kernel, cudaFuncAttributeMaxDynamicSharedMemorySize,
                       ATTN_SMEM);

  // prep
  {
    int n = NTOK * DMODEL;
    split_kernel<<<(n + 255) / 256, 256>>>(x, xh, xl, n);
  }
  wsplit_kernel<<<dim3((NH*HDIM)/32, DMODEL/32), dim3(32, 8)>>>(Wq, wqh, wql, DMODEL, NH*HDIM);
  wsplit_kernel<<<dim3((NKV*HDIM)/32, DMODEL/32), dim3(32, 8)>>>(Wk, wkh, wkl, DMODEL, NKV*HDIM);
  wsplit_kernel<<<dim3((NKV*HDIM)/32, DMODEL/32), dim3(32, 8)>>>(Wv, wvh, wvl, DMODEL, NKV*HDIM);
  wsplit_kernel<<<dim3(DMODEL/32, DMODEL/32), dim3(32, 8)>>>(Wo, woh, wol, DMODEL, DMODEL);

  // QKV projections (V writes split bf16 directly)
  gemm3_kernel<<<dim3((NH*HDIM)/GBN, NTOK/GBM), 256, GEMM_SMEM>>>(
      xh, xl, wqh, wql, gq, nullptr, nullptr, DMODEL, NH*HDIM);
  gemm3_kernel<<<dim3((NKV*HDIM)/GBN, NTOK/GBM), 256, GEMM_SMEM>>>(
      xh, xl, wkh, wkl, gk, nullptr, nullptr, DMODEL, NKV*HDIM);
  gemm3_kernel<<<dim3((NKV*HDIM)/GBN, NTOK/GBM), 256, GEMM_SMEM>>>(
      xh, xl, wvh, wvl, nullptr, vbh, vbl, DMODEL, NKV*HDIM);

  // RoPE + l2norm -> split bf16 q/k
  rope_norm_kernel<<<dim3(NTOK, NH + NKV), 64>>>();

  // attention (writes attn probs + split ctx)
  attn_mma_kernel<<<dim3(SEQ / 16, NH, BATCH), 256, ATTN_SMEM>>>(attn, write_attn);

  // output projection
  gemm3_kernel<<<dim3(DMODEL/GBN, NTOK/GBM), 256, GEMM_SMEM>>>(
      cth, ctl, woh, wol, out, nullptr, nullptr, DMODEL, DMODEL);
}